// round 17
// baseline (speedup 1.0000x reference)
#include <cuda_runtime.h>
#include <cuda_fp16.h>
#include <math.h>
#include <mma.h>

// ---------------------------------------------------------------------------
// SimGNN on GB300: two anti-phased streams; fp16 activations end-to-end
// (fp32 math); fp16 tensor-core GEMMs; batched CSR build (proven scan
// kernels); colsum fused into final aggregation.
// ---------------------------------------------------------------------------

#define MAXN 100000
#define MAXE 1300000
#define XCAP ((size_t)MAXN * 128)

using namespace nvcuda;

__device__ __align__(16) float g_bufA[2 * XCAP];
__device__ __align__(16) float g_bufB[2 * XCAP];
__device__ __align__(16) float g_bufC[2 * XCAP];
__device__ __align__(16) float g_dinv[2 * MAXN];
__device__ __align__(16) int   g_deg [2 * MAXN];
__device__ __align__(16) int   g_off [2 * (MAXN + 1)];
__device__ __align__(16) int   g_cur [2 * MAXN];
__device__ __align__(16) int   g_part[2 * 256];
__device__ __align__(16) int2  g_csr [2 * (size_t)MAXE];
__device__ __align__(16) float g_colsum[2 * 64];
__device__ __align__(16) float g_gc[2 * 64];
__device__ __align__(16) float g_h[128];

static cudaStream_t g_s2;
static cudaEvent_t  g_evFork, g_evJoin, g_evCsr0;
namespace {
struct StreamInit {
    StreamInit() {
        cudaStreamCreateWithFlags(&g_s2, cudaStreamNonBlocking);
        cudaEventCreateWithFlags(&g_evFork, cudaEventDisableTiming);
        cudaEventCreateWithFlags(&g_evJoin, cudaEventDisableTiming);
        cudaEventCreateWithFlags(&g_evCsr0, cudaEventDisableTiming);
    }
};
static StreamInit s_streamInit;
}

// ------------------------- type-generic loads/stores -----------------------
__device__ __forceinline__ float4 load4(const float* p) { return *(const float4*)p; }
__device__ __forceinline__ float4 load4(const __half* p) {
    const __half2* h = (const __half2*)p;
    float2 a = __half22float2(h[0]);
    float2 b = __half22float2(h[1]);
    return make_float4(a.x, a.y, b.x, b.y);
}
__device__ __forceinline__ float2 load2(const float* p) { return *(const float2*)p; }
__device__ __forceinline__ float2 load2(const __half* p) {
    return __half22float2(*(const __half2*)p);
}
__device__ __forceinline__ void store4(float* p, float4 v) { *(float4*)p = v; }
__device__ __forceinline__ void store4(__half* p, float4 v) {
    __half2* h = (__half2*)p;
    h[0] = __floats2half2_rn(v.x, v.y);
    h[1] = __floats2half2_rn(v.z, v.w);
}
__device__ __forceinline__ void store2(float* p, float2 v) { *(float2*)p = v; }
__device__ __forceinline__ void store2(__half* p, float2 v) {
    *(__half2*)p = __floats2half2_rn(v.x, v.y);
}

// ---------------------------------------------------------------------------
__global__ void zero_all_kernel(int* __restrict__ deg, float* __restrict__ h,
                                float* __restrict__ colsum, int n2)
{
    int i = blockIdx.x * blockDim.x + threadIdx.x;
    if (i < n2) deg[i] = 0;
    if (i < 128) { h[i] = 0.f; colsum[i] = 0.f; }
}

__global__ void f2h_kernel(const float* __restrict__ in, __half* __restrict__ out, int n4)
{
    int i = blockIdx.x * blockDim.x + threadIdx.x;
    if (i < n4) {
        float4 v = ((const float4*)in)[i];
        store4(out + i * 4, v);
    }
}

// grid.y = graph (batched, R6-proven pattern)
__global__ void deg_kernel(const int* __restrict__ e0, const int* __restrict__ e1,
                           int* __restrict__ deg, int E) {
    int g = blockIdx.y;
    const int* dst = (g ? e1 : e0) + E;
    int i = blockIdx.x * blockDim.x + threadIdx.x;
    if (i < E) atomicAdd(&deg[g * MAXN + dst[i]], 1);
}

// --------------------------- CSR build: scan (R15-proven, batched) ---------
__global__ void scan1_kernel(const int* __restrict__ deg, int* __restrict__ off,
                             int* __restrict__ partials, int n)
{
    __shared__ int wsum[32];
    int g = blockIdx.y;
    deg += g * MAXN; off += g * (MAXN + 1); partials += g * 256;
    int gid  = blockIdx.x * 1024 + threadIdx.x;
    int lane = threadIdx.x & 31, wid = threadIdx.x >> 5;
    int v = (gid < n) ? deg[gid] : 0;
    int x = v;
#pragma unroll
    for (int o = 1; o < 32; o <<= 1) {
        int y = __shfl_up_sync(0xFFFFFFFFu, x, o);
        if (lane >= o) x += y;
    }
    if (lane == 31) wsum[wid] = x;
    __syncthreads();
    if (wid == 0) {
        int s = wsum[lane];
#pragma unroll
        for (int o = 1; o < 32; o <<= 1) {
            int y = __shfl_up_sync(0xFFFFFFFFu, s, o);
            if (lane >= o) s += y;
        }
        wsum[lane] = s;
    }
    __syncthreads();
    int excl = (wid > 0 ? wsum[wid - 1] : 0) + x - v;
    if (gid < n) off[gid] = excl;
    if (threadIdx.x == 1023) partials[blockIdx.x] = wsum[31];
}

// grid.x = graph (one block per graph)
__global__ void scan2_kernel(int* __restrict__ partials, int nb)
{
    __shared__ int wsum[4];
    int g = blockIdx.x;
    partials += g * 256;
    int t = threadIdx.x;
    int lane = t & 31, w = t >> 5;
    int v = (t < nb) ? partials[t] : 0;
    int x = v;
#pragma unroll
    for (int o = 1; o < 32; o <<= 1) {
        int y = __shfl_up_sync(0xFFFFFFFFu, x, o);
        if (lane >= o) x += y;
    }
    if (lane == 31) wsum[w] = x;
    __syncthreads();
    if (w == 0 && lane < 4) {
        int s = wsum[lane];
#pragma unroll
        for (int o = 1; o < 4; o <<= 1) {
            int y = __shfl_up_sync(0x0000000Fu, s, o);
            if (lane >= o) s += y;
        }
        wsum[lane] = s;
    }
    __syncthreads();
    int incl = x + (w > 0 ? wsum[w - 1] : 0);
    if (t < nb) partials[t] = incl - v;
}

__global__ void scan3_kernel(int* __restrict__ off, const int* __restrict__ partials,
                             int* __restrict__ cur, const int* __restrict__ deg,
                             float* __restrict__ dinv, int n)
{
    int g = blockIdx.y;
    off += g * (MAXN + 1); partials += g * 256; cur += g * MAXN;
    deg += g * MAXN; dinv += g * MAXN;
    int gid = blockIdx.x * blockDim.x + threadIdx.x;
    if (gid < n) {
        int o = off[gid] + partials[gid >> 10];
        off[gid] = o;
        cur[gid] = o;
        if (gid == n - 1) off[n] = o + deg[gid];
        dinv[gid] = rsqrtf((float)(deg[gid] + 1));
    }
}

__global__ void scatter_kernel(const int* __restrict__ e0, const int* __restrict__ e1,
                               const float* __restrict__ dinv, int* __restrict__ cur,
                               int2* __restrict__ csr, int E)
{
    int g = blockIdx.y;
    const int* eidx = g ? e1 : e0;
    dinv += g * MAXN; cur += g * MAXN; csr += (size_t)g * MAXE;
    int e = blockIdx.x * blockDim.x + threadIdx.x;
    if (e >= E) return;
    int s = eidx[e], d = eidx[E + e];
    int pos = atomicAdd(&cur[d], 1);
    csr[pos] = make_int2(s, __float_as_int(__ldg(&dinv[s])));
}

// ---------------------------------------------------------------------------
// fp16 tensor-core GEMM (R13-proven): xwH = relu_fused(in) @ W.
template<typename TIN, int DIN, int DOUT, bool FUSE>
__global__ void __launch_bounds__(256)
gemm_kernel(const TIN* __restrict__ in, const float* __restrict__ W,
            const float* __restrict__ bprev, __half* __restrict__ xw, int n)
{
    constexpr int WS = DOUT + 16;
    constexpr int XS = DIN + 16;
    constexpr int CT = DOUT / 16;
    constexpr int NT = CT / 2;

    extern __shared__ __half shh[];
    __half* Ws = shh;
    __half* xs = shh + DIN * WS;
    float*  stage = (float*)(xs + 64 * XS);

    const int tid  = threadIdx.x;
    const int w    = tid >> 5;
    const int lane = tid & 31;

    for (int i = tid; i < DIN * DOUT / 4; i += 256) {
        int row = i / (DOUT / 4), c4 = i % (DOUT / 4);
        float4 v = ((const float4*)(W + row * DOUT))[c4];
        __half2* d = (__half2*)(Ws + row * WS + c4 * 4);
        d[0] = __floats2half2_rn(v.x, v.y);
        d[1] = __floats2half2_rn(v.z, v.w);
    }

    const int row0 = blockIdx.x * 64;
    for (int i = tid; i < 64 * DIN / 4; i += 256) {
        int r = i / (DIN / 4), kk = i % (DIN / 4);
        int row = row0 + r;
        float4 v = make_float4(0.f, 0.f, 0.f, 0.f);
        if (row < n) {
            v = load4(in + (size_t)row * DIN + kk * 4);
            if (FUSE) {
                float4 b = ((const float4*)bprev)[kk];
                v.x = fmaxf(v.x + b.x, 0.f);
                v.y = fmaxf(v.y + b.y, 0.f);
                v.z = fmaxf(v.z + b.z, 0.f);
                v.w = fmaxf(v.w + b.w, 0.f);
            }
        }
        __half2* d = (__half2*)(xs + r * XS + kk * 4);
        d[0] = __floats2half2_rn(v.x, v.y);
        d[1] = __floats2half2_rn(v.z, v.w);
    }
    __syncthreads();

    const int rt  = w >> 1;
    const int ctb = (w & 1) * NT;

    wmma::fragment<wmma::accumulator, 16, 16, 16, float> acc[NT];
#pragma unroll
    for (int t = 0; t < NT; t++) wmma::fill_fragment(acc[t], 0.f);

#pragma unroll
    for (int k0 = 0; k0 < DIN; k0 += 16) {
        wmma::fragment<wmma::matrix_a, 16, 16, 16, __half, wmma::row_major> a;
        wmma::load_matrix_sync(a, xs + rt * 16 * XS + k0, XS);
#pragma unroll
        for (int t = 0; t < NT; t++) {
            wmma::fragment<wmma::matrix_b, 16, 16, 16, __half, wmma::row_major> b;
            wmma::load_matrix_sync(b, Ws + k0 * WS + (ctb + t) * 16, WS);
            wmma::mma_sync(acc[t], a, b, acc[t]);
        }
    }

    const int trow = row0 + rt * 16;
    if (trow < n) {
        float* st = stage + w * 256;
#pragma unroll
        for (int t = 0; t < NT; t++) {
            wmma::store_matrix_sync(st, acc[t], 16, wmma::mem_row_major);
            __syncwarp();
#pragma unroll
            for (int q = 0; q < 4; q++) {
                int idx = lane + q * 32;
                int r = idx >> 3, c = (idx & 7) * 2;
                if (trow + r < n)
                    *(__half2*)(xw + (size_t)(trow + r) * DOUT + (ctb + t) * 16 + c) =
                        __floats2half2_rn(st[r * 16 + c], st[r * 16 + c + 1]);
            }
            __syncwarp();
        }
    }
}

// ---------------------------------------------------------------------------
// CSR aggregation (fp32 accumulate, 4-edge unroll). CS: fused column sums.
template<typename TIN, typename TOUT, int DOUT, bool CS>
__global__ void agg_csr_kernel(const int* __restrict__ off, const int2* __restrict__ csr,
                               const TIN* __restrict__ xw, const float* __restrict__ dinv,
                               TOUT* __restrict__ aggout, float* __restrict__ colsum, int n)
{
    constexpr int VEC = DOUT / 32;   // 4 or 2
    __shared__ float csm[8][64];
    int node = blockIdx.x * 8 + (threadIdx.x >> 5);
    int lane = threadIdx.x & 31;
    int w = threadIdx.x >> 5;

    float acc[VEC], acc2[VEC];
#pragma unroll
    for (int q = 0; q < VEC; q++) { acc[q] = 0.f; acc2[q] = 0.f; }

    if (node < n) {
        float dv = __ldg(&dinv[node]);
        const TIN* xr = xw + (size_t)node * DOUT + lane * VEC;
        if (VEC == 4) {
            float4 v = load4(xr);
            acc[0] = v.x * dv * dv; acc[1] = v.y * dv * dv;
            acc[2] = v.z * dv * dv; acc[3] = v.w * dv * dv;
        } else {
            float2 v = load2(xr);
            acc[0] = v.x * dv * dv; acc[1] = v.y * dv * dv;
        }

        int p = __ldg(&off[node]);
        int pend = __ldg(&off[node + 1]);
        for (; p + 4 <= pend; p += 4) {
            int2 e0 = __ldg(&csr[p]);
            int2 e1 = __ldg(&csr[p + 1]);
            int2 e2 = __ldg(&csr[p + 2]);
            int2 e3 = __ldg(&csr[p + 3]);
            float n0 = __int_as_float(e0.y) * dv;
            float n1 = __int_as_float(e1.y) * dv;
            float n2 = __int_as_float(e2.y) * dv;
            float n3 = __int_as_float(e3.y) * dv;
            const TIN* s0 = xw + (size_t)e0.x * DOUT + lane * VEC;
            const TIN* s1 = xw + (size_t)e1.x * DOUT + lane * VEC;
            const TIN* s2 = xw + (size_t)e2.x * DOUT + lane * VEC;
            const TIN* s3 = xw + (size_t)e3.x * DOUT + lane * VEC;
            if (VEC == 4) {
                float4 v0 = load4(s0), v1 = load4(s1), v2 = load4(s2), v3 = load4(s3);
                acc[0] = fmaf(n0, v0.x, acc[0]);  acc[1] = fmaf(n0, v0.y, acc[1]);
                acc[2] = fmaf(n0, v0.z, acc[2]);  acc[3] = fmaf(n0, v0.w, acc[3]);
                acc2[0] = fmaf(n1, v1.x, acc2[0]); acc2[1] = fmaf(n1, v1.y, acc2[1]);
                acc2[2] = fmaf(n1, v1.z, acc2[2]); acc2[3] = fmaf(n1, v1.w, acc2[3]);
                acc[0] = fmaf(n2, v2.x, acc[0]);  acc[1] = fmaf(n2, v2.y, acc[1]);
                acc[2] = fmaf(n2, v2.z, acc[2]);  acc[3] = fmaf(n2, v2.w, acc[3]);
                acc2[0] = fmaf(n3, v3.x, acc2[0]); acc2[1] = fmaf(n3, v3.y, acc2[1]);
                acc2[2] = fmaf(n3, v3.z, acc2[2]); acc2[3] = fmaf(n3, v3.w, acc2[3]);
            } else {
                float2 v0 = load2(s0), v1 = load2(s1), v2 = load2(s2), v3 = load2(s3);
                acc[0] = fmaf(n0, v0.x, acc[0]);  acc[1] = fmaf(n0, v0.y, acc[1]);
                acc2[0] = fmaf(n1, v1.x, acc2[0]); acc2[1] = fmaf(n1, v1.y, acc2[1]);
                acc[0] = fmaf(n2, v2.x, acc[0]);  acc[1] = fmaf(n2, v2.y, acc[1]);
                acc2[0] = fmaf(n3, v3.x, acc2[0]); acc2[1] = fmaf(n3, v3.y, acc2[1]);
            }
        }
        for (; p < pend; p++) {
            int2 e0 = __ldg(&csr[p]);
            float n0 = __int_as_float(e0.y) * dv;
            const TIN* s0 = xw + (size_t)e0.x * DOUT + lane * VEC;
            if (VEC == 4) {
                float4 v0 = load4(s0);
                acc[0] = fmaf(n0, v0.x, acc[0]); acc[1] = fmaf(n0, v0.y, acc[1]);
                acc[2] = fmaf(n0, v0.z, acc[2]); acc[3] = fmaf(n0, v0.w, acc[3]);
            } else {
                float2 v0 = load2(s0);
                acc[0] = fmaf(n0, v0.x, acc[0]); acc[1] = fmaf(n0, v0.y, acc[1]);
            }
        }

#pragma unroll
        for (int q = 0; q < VEC; q++) acc[q] += acc2[q];

        TOUT* o = aggout + (size_t)node * DOUT + lane * VEC;
        if (VEC == 4)
            store4(o, make_float4(acc[0], acc[1], acc[2], acc[3]));
        else
            store2(o, make_float2(acc[0], acc[1]));
    }

    if (CS) {
        // fused column sums (DOUT==64, VEC==2): block reduce, 64 atomics
        csm[w][2 * lane]     = (node < n) ? acc[0] : 0.f;
        csm[w][2 * lane + 1] = (node < n) ? acc[1] : 0.f;
        __syncthreads();
        if (threadIdx.x < 64) {
            float s = 0.f;
#pragma unroll
            for (int i = 0; i < 8; i++) s += csm[i][threadIdx.x];
            atomicAdd(&colsum[threadIdx.x], s);
        }
    }
}

// ---------------------------------------------------------------------------
__global__ void gc_kernel(const float* __restrict__ colsum, const float* __restrict__ b2,
                          const float* __restrict__ Wa, float* __restrict__ gc, float invN)
{
    __shared__ float mean[64];
    int t = threadIdx.x;
    mean[t] = colsum[t] * invN + b2[t];
    __syncthreads();
    float acc = 0.f;
#pragma unroll
    for (int d = 0; d < 64; d++) acc += mean[d] * Wa[d * 64 + t];
    gc[t] = tanhf(acc);
}

template<typename T>
__global__ void attpool_kernel(const T* __restrict__ agg, const float* __restrict__ b2,
                               const float* __restrict__ gc, float* __restrict__ h, int n)
{
    __shared__ float gcs[64], b2s[64];
    __shared__ float red[8][64];
    int tid = threadIdx.x;
    if (tid < 64) { gcs[tid] = gc[tid]; b2s[tid] = b2[tid]; }
    __syncthreads();
    int lane = tid & 31, w = tid >> 5;
    float gx = gcs[2 * lane], gy = gcs[2 * lane + 1];
    float bx = b2s[2 * lane], by = b2s[2 * lane + 1];
    float ax = 0.f, ay = 0.f;
    for (int row = blockIdx.x * 8 + w; row < n; row += gridDim.x * 8) {
        float2 v = load2(agg + (size_t)row * 64 + 2 * lane);
        v.x += bx; v.y += by;
        float d = v.x * gx + v.y * gy;
#pragma unroll
        for (int o = 16; o; o >>= 1) d += __shfl_xor_sync(0xFFFFFFFFu, d, o);
        float att = 1.f / (1.f + expf(-d));
        ax += v.x * att; ay += v.y * att;
    }
    red[w][2 * lane] = ax; red[w][2 * lane + 1] = ay;
    __syncthreads();
    if (w == 0) {
        float sx = 0.f, sy = 0.f;
#pragma unroll
        for (int i = 0; i < 8; i++) { sx += red[i][2 * lane]; sy += red[i][2 * lane + 1]; }
        atomicAdd(&h[2 * lane], sx);
        atomicAdd(&h[2 * lane + 1], sy);
    }
}

// ---------------------------------------------------------------------------
__global__ void final_kernel(const float* __restrict__ h,
                             const float* __restrict__ Wt, const float* __restrict__ Wm,
                             const float* __restrict__ nb,
                             const float* __restrict__ w0, const float* __restrict__ bb0,
                             const float* __restrict__ w1, const float* __restrict__ bb1,
                             const float* __restrict__ w2, const float* __restrict__ bb2,
                             const float* __restrict__ w3, const float* __restrict__ bb3,
                             const float* __restrict__ sw, const float* __restrict__ sb,
                             float* __restrict__ out)
{
    __shared__ float hi[64], hj[64];
    __shared__ float part[1024];
    __shared__ float z[16];
    int t = threadIdx.x;
    if (t < 64) hi[t] = h[t];
    else if (t < 128) hj[t - 64] = h[t];
    __syncthreads();

    int k = t >> 6, e = t & 63;
    const float* wt = Wt + (size_t)k * 4096 + e;
    float acc = 0.f;
#pragma unroll
    for (int d = 0; d < 64; d++) acc += hi[d] * wt[d * 64];
    part[t] = acc * hj[e];
    __syncthreads();

    if (t < 16) {
        float s = 0.f;
        for (int e2 = 0; e2 < 64; e2++) s += part[t * 64 + e2];
        float lin = 0.f;
        const float* wm = Wm + t * 128;
        for (int m = 0; m < 64; m++) lin += wm[m] * hi[m] + wm[64 + m] * hj[m];
        z[t] = tanhf(s + lin + nb[t]);
    }
    __syncthreads();

    if (t == 0) {
        float a[32], b[32];
        for (int j = 0; j < 32; j++) { float s = bb0[j]; for (int i = 0; i < 16; i++) s += z[i] * w0[i * 32 + j]; a[j] = fmaxf(s, 0.f); }
        for (int j = 0; j < 16; j++) { float s = bb1[j]; for (int i = 0; i < 32; i++) s += a[i] * w1[i * 16 + j]; b[j] = fmaxf(s, 0.f); }
        for (int j = 0; j <  8; j++) { float s = bb2[j]; for (int i = 0; i < 16; i++) s += b[i] * w2[i * 8 + j];  a[j] = fmaxf(s, 0.f); }
        for (int j = 0; j <  4; j++) { float s = bb3[j]; for (int i = 0; i <  8; i++) s += a[i] * w3[i * 4 + j];  b[j] = fmaxf(s, 0.f); }
        float s = sb[0];
        for (int i = 0; i < 4; i++) s += b[i] * sw[i];
        out[0] = s;
    }
}

// ---------------------------------------------------------------------------
extern "C" void kernel_launch(void* const* d_in, const int* in_sizes, int n_in,
                              void* d_out, int out_size)
{
    const float* x_i = (const float*)d_in[0];
    const int*   ei  = (const int*)d_in[1];     // int32 (JAX x64 disabled)
    const float* x_j = (const float*)d_in[2];
    const int*   ej  = (const int*)d_in[3];
    const float* w0 = (const float*)d_in[4];
    const float* b0 = (const float*)d_in[5];
    const float* w1 = (const float*)d_in[6];
    const float* b1 = (const float*)d_in[7];
    const float* w2 = (const float*)d_in[8];
    const float* b2 = (const float*)d_in[9];
    const float* att_w  = (const float*)d_in[10];
    const float* ntn_wt = (const float*)d_in[11];
    const float* ntn_wm = (const float*)d_in[12];
    const float* ntn_b  = (const float*)d_in[13];
    const float* mw0 = (const float*)d_in[14];
    const float* mb0 = (const float*)d_in[15];
    const float* mw1 = (const float*)d_in[16];
    const float* mb1 = (const float*)d_in[17];
    const float* mw2 = (const float*)d_in[18];
    const float* mb2 = (const float*)d_in[19];
    const float* mw3 = (const float*)d_in[20];
    const float* mb3 = (const float*)d_in[21];
    const float* sw  = (const float*)d_in[22];
    const float* sb  = (const float*)d_in[23];
    float* out = (float*)d_out;

    const int N = in_sizes[0] / 64;
    const int E = in_sizes[1] / 2;

    float *bufA, *bufB, *bufC, *dinvp, *colsump, *gcp, *hp;
    int *degp, *offp, *curp, *partp;
    int2* csrp;
    cudaGetSymbolAddress((void**)&bufA,    g_bufA);
    cudaGetSymbolAddress((void**)&bufB,    g_bufB);
    cudaGetSymbolAddress((void**)&bufC,    g_bufC);
    cudaGetSymbolAddress((void**)&dinvp,   g_dinv);
    cudaGetSymbolAddress((void**)&degp,    g_deg);
    cudaGetSymbolAddress((void**)&offp,    g_off);
    cudaGetSymbolAddress((void**)&curp,    g_cur);
    cudaGetSymbolAddress((void**)&partp,   g_part);
    cudaGetSymbolAddress((void**)&csrp,    g_csr);
    cudaGetSymbolAddress((void**)&colsump, g_colsum);
    cudaGetSymbolAddress((void**)&gcp,     g_gc);
    cudaGetSymbolAddress((void**)&hp,      g_h);

    const int smem0 = (64  * 144 + 64 * 80 ) * 2 + 8192;
    const int smem1 = (128 * 144 + 64 * 144) * 2 + 8192;
    const int smem2 = (128 * 80  + 64 * 144) * 2 + 8192;
    cudaFuncSetAttribute(gemm_kernel<float, 64, 128, false>, cudaFuncAttributeMaxDynamicSharedMemorySize, smem0);
    cudaFuncSetAttribute(gemm_kernel<__half, 64, 128, false>, cudaFuncAttributeMaxDynamicSharedMemorySize, smem0);
    cudaFuncSetAttribute(gemm_kernel<__half, 128, 128, true>, cudaFuncAttributeMaxDynamicSharedMemorySize, smem1);
    cudaFuncSetAttribute(gemm_kernel<__half, 128, 64,  true>, cudaFuncAttributeMaxDynamicSharedMemorySize, smem2);

    const int gemm_blocks = (N + 63) / 64;
    const int agg_blocks  = (N + 7) / 8;
    const int scan_blocks = (N + 1023) / 1024;
    const dim3 nb256_2((N + 255) / 256, 2);
    const dim3 eb256_2((E + 255) / 256, 2);

    cudaStream_t s0 = 0;
    cudaStream_t s1 = g_s2;

    zero_all_kernel<<<(2 * N + 255) / 256, 256, 0, s0>>>(degp, hp, colsump, 2 * N);
    cudaEventRecord(g_evFork, s0);
    cudaStreamWaitEvent(s1, g_evFork, 0);

    __half* hX0 = (__half*)bufB;
    __half* hG0 = (__half*)bufA;
    __half* hC0 = (__half*)bufC;
    __half* hX1 = (__half*)(bufB + XCAP);
    __half* hG1 = (__half*)(bufA + XCAP);
    __half* hC1 = (__half*)(bufC + XCAP);
    __half* hXj = hC1 + XCAP / 2;

    // ---- s0: graph-0 L0 GEMM (no CSR dependency) overlaps batched CSR on s1
    gemm_kernel<float, 64, 128, false><<<gemm_blocks, 256, smem0, s0>>>(x_i, w0, nullptr, hX0, N);

    // ---- s1: x_j->fp16 + batched CSR build for BOTH graphs (proven kernels)
    f2h_kernel<<<(N * 64 / 4 + 255) / 256, 256, 0, s1>>>(x_j, hXj, N * 64 / 4);
    deg_kernel<<<eb256_2, 256, 0, s1>>>(ei, ej, degp, E);
    scan1_kernel<<<dim3(scan_blocks, 2), 1024, 0, s1>>>(degp, offp, partp, N);
    scan2_kernel<<<2, 128, 0, s1>>>(partp, scan_blocks);
    scan3_kernel<<<nb256_2, 256, 0, s1>>>(offp, partp, curp, degp, dinvp, N);
    scatter_kernel<<<eb256_2, 256, 0, s1>>>(ei, ej, dinvp, curp, csrp, E);
    cudaEventRecord(g_evCsr0, s1);
    cudaStreamWaitEvent(s0, g_evCsr0, 0);    // release s0's aggs

    // ================= graph 0 (s0) =================
    {
        const int* off = offp;
        const int2* csr = csrp;
        const float* dnv = dinvp;
        agg_csr_kernel<__half, __half, 128, false><<<agg_blocks, 256, 0, s0>>>(off, csr, hX0, dnv, hG0, nullptr, N);
        gemm_kernel<__half, 128, 128, true><<<gemm_blocks, 256, smem1, s0>>>(hG0, w1, b0, hX0, N);
        agg_csr_kernel<__half, __half, 128, false><<<agg_blocks, 256, 0, s0>>>(off, csr, hX0, dnv, hG0, nullptr, N);
        gemm_kernel<__half, 128, 64, true><<<gemm_blocks, 256, smem2, s0>>>(hG0, w2, b1, hX0, N);
        agg_csr_kernel<__half, __half, 64, true><<<agg_blocks, 256, 0, s0>>>(off, csr, hX0, dnv, hC0, colsump, N);
        gc_kernel<<<1, 64, 0, s0>>>(colsump, b2, att_w, gcp, 1.0f / (float)N);
        attpool_kernel<__half><<<592, 256, 0, s0>>>(hC0, b2, gcp, hp, N);
    }

    // ================= graph 1 (s1) =================
    {
        const int* off = offp + (MAXN + 1);
        const int2* csr = csrp + (size_t)MAXE;
        const float* dnv = dinvp + MAXN;
        agg_csr_kernel<__half, __half, 64, false><<<agg_blocks, 256, 0, s1>>>(off, csr, hXj, dnv, hG1, nullptr, N);
        gemm_kernel<__half, 64, 128, false><<<gemm_blocks, 256, smem0, s1>>>(hG1, w0, nullptr, hX1, N);
        gemm_kernel<__half, 128, 128, true><<<gemm_blocks, 256, smem1, s1>>>(hX1, w1, b0, hG1, N);
        agg_csr_kernel<__half, __half, 128, false><<<agg_blocks, 256, 0, s1>>>(off, csr, hG1, dnv, hX1, nullptr, N);
        gemm_kernel<__half, 128, 64, true><<<gemm_blocks, 256, smem2, s1>>>(hX1, w2, b1, hG1, N);
        agg_csr_kernel<__half, __half, 64, true><<<agg_blocks, 256, 0, s1>>>(off, csr, hG1, dnv, hC1, colsump + 64, N);
        gc_kernel<<<1, 64, 0, s1>>>(colsump + 64, b2, att_w, gcp + 64, 1.0f / (float)N);
        attpool_kernel<__half><<<592, 256, 0, s1>>>(hC1, b2, gcp + 64, hp + 64, N);
    }

    cudaEventRecord(g_evJoin, s1);
    cudaStreamWaitEvent(s0, g_evJoin, 0);

    final_kernel<<<1, 1024, 0, s0>>>(hp, ntn_wt, ntn_wm, ntn_b,
                                     mw0, mb0, mw1, mb1, mw2, mb2, mw3, mb3,
                                     sw, sb, out);
}